// round 15
// baseline (speedup 1.0000x reference)
#include <cuda_runtime.h>
#include <cuda_bf16.h>
#include <math.h>
#include <stdint.h>

// Problem constants
#define B_TOT   4096
#define T_STEPS 25
#define K_ENS   8
#define OBS     64
#define ACT     16
#define IN1     80
#define HID     512
#define OUTD    129
#define N3PAD   136
#define TM      32
#define NTHREADS 512          // 16 warps
#define SETUP_THREADS 256
#define MAXTILES 144          // even-padded per member
#define OUT_STRIDE 132

// kit counts
#define NKIT1   (IN1/16)      // 5
#define NKIT2   (HID/16)      // 32
#define NKIT3   (HID/16)      // 32
#define NT1     (HID/8)       // 64 n8-tiles
#define NT3     (N3PAD/8)     // 17

// weight stream (per member, kit-major chunks)
#define L1_BYTES   (NKIT1*NT1*32*16)                 // 163840
#define L2_BYTES   (NKIT2*NT1*32*16)                 // 1048576
#define L3_BYTES   (NKIT3*NT3*32*16)                 // 278528
#define L2_BASE    L1_BYTES
#define L3_BASE    (L1_BYTES + L2_BYTES)             // 1212416
#define STREAM_BYTES (L1_BYTES + L2_BYTES + L3_BYTES) // 1490944
#define CHUNKS_PER_STEP 69
#define TOTAL_CHUNKS (T_STEPS * CHUNKS_PER_STEP)     // 1725

// ring
#define RING 4
#define SLOT_BYTES 32768

// activation smem strides (bf16 elems)
#define XS      88
#define HS      520

// dynamic smem layout (bytes)
#define OFF_HH   0
#define OFF_HL   (OFF_HH + TM*HS*2)
#define OFF_XH   (OFF_HL + TM*HS*2)
#define OFF_XL   (OFF_XH + TM*XS*2)
#define OFF_OUT  (OFF_XL + TM*XS*2)
#define OFF_B1   (OFF_OUT + TM*OUT_STRIDE*4)
#define OFF_B2   (OFF_B1 + HID*4)
#define OFF_B3   (OFF_B2 + HID*4)
#define OFF_RING (((OFF_B3 + N3PAD*4) + 1023) & ~1023)
#define SMEM_BYTES (OFF_RING + RING*SLOT_BYTES)

// ---- device-global scratch ----
__device__ int g_perm[B_TOT];
__device__ int g_tileK[MAXTILES];
__device__ int g_tileStart[MAXTILES];
__device__ int g_tileRows[MAXTILES];
__device__ int g_ntiles;

__device__ __align__(16) unsigned char g_ws[(size_t)K_ENS * STREAM_BYTES];

// ---- mbarrier / bulk-async PTX ----
#define MBAR_INIT(addr, cnt) \
    asm volatile("mbarrier.init.shared.b64 [%0], %1;" :: "r"(addr), "r"(cnt) : "memory")
#define MBAR_EXPECT_TX(addr, bytes) \
    asm volatile("mbarrier.arrive.expect_tx.shared.b64 _, [%0], %1;" :: "r"(addr), "r"(bytes) : "memory")
#define MBAR_ARRIVE(addr) \
    asm volatile("mbarrier.arrive.shared.b64 _, [%0];" :: "r"(addr) : "memory")
#define ARRIVE_PEER(addr, prank) \
    asm volatile("{\n\t.reg .b32 r;\n\tmapa.shared::cluster.u32 r, %0, %1;\n\t" \
                 "mbarrier.arrive.shared::cluster.b64 _, [r];\n\t}" \
                 :: "r"(addr), "r"(prank) : "memory")
#define MBAR_WAIT_ACQ(addr, ph) do { unsigned _done = 0; \
    while (!_done) { \
        asm volatile("{\n\t.reg .pred p;\n\t" \
            "mbarrier.try_wait.parity.acquire.cta.shared::cta.b64 p, [%1], %2, 0x989680;\n\t" \
            "selp.b32 %0, 1, 0, p;\n\t}" \
            : "=r"(_done) : "r"(addr), "r"((unsigned)(ph)) : "memory"); \
    } } while (0)
#define MBAR_WAIT_RLX(addr, ph) do { unsigned _done = 0; \
    while (!_done) { \
        asm volatile("{\n\t.reg .pred p;\n\t" \
            "mbarrier.try_wait.parity.relaxed.cta.shared::cta.b64 p, [%1], %2, 0x989680;\n\t" \
            "selp.b32 %0, 1, 0, p;\n\t}" \
            : "=r"(_done) : "r"(addr), "r"((unsigned)(ph)) : "memory"); \
    } } while (0)
#define CP_BULK(dst, src, bytes, mbar) \
    asm volatile("cp.async.bulk.shared::cluster.global.mbarrier::complete_tx::bytes [%0], [%1], %2, [%3];" \
        :: "r"(dst), "l"(src), "r"(bytes), "r"(mbar) : "memory")
#define CP_BULK_MC(dst, src, bytes, mbar, mask) \
    asm volatile("cp.async.bulk.shared::cluster.global.mbarrier::complete_tx::bytes.multicast::cluster [%0], [%1], %2, [%3], %4;" \
        :: "r"(dst), "l"(src), "r"(bytes), "r"(mbar), "h"((uint16_t)(mask)) : "memory")
#define CLUSTER_SYNC() do { \
    asm volatile("barrier.cluster.arrive.aligned;" ::: "memory"); \
    asm volatile("barrier.cluster.wait.aligned;" ::: "memory"); } while (0)

__device__ __forceinline__ uint32_t smem_u32(const void* p) {
    uint32_t a;
    asm("{ .reg .u64 t; cvta.to.shared.u64 t, %1; cvt.u32.u64 %0, t; }" : "=r"(a) : "l"(p));
    return a;
}
__device__ __forceinline__ uint32_t ctarank() {
    uint32_t r; asm("mov.u32 %0, %%cluster_ctarank;" : "=r"(r)); return r;
}

// ============================================================
// Setup: dtype-detect + counting sort; tiles even-padded per member.
// ============================================================
__global__ void setup_kernel(const int* __restrict__ assign_raw) {
    __shared__ int cnt[K_ENS];
    __shared__ int cur[K_ENS];
    __shared__ int odd_nonzero;
    int tid = threadIdx.x;
    if (tid < K_ENS) cnt[tid] = 0;
    if (tid == 0) odd_nonzero = 0;
    __syncthreads();

    int local_nz = 0;
    for (int w = 2 * tid + 1; w < B_TOT; w += 2 * SETUP_THREADS)
        if (assign_raw[w] != 0) local_nz = 1;
    if (local_nz) atomicOr(&odd_nonzero, 1);
    __syncthreads();
    const bool is_i32 = (odd_nonzero != 0);

    for (int b = tid; b < B_TOT; b += SETUP_THREADS) {
        int k = is_i32 ? assign_raw[b] : assign_raw[2 * b];
        atomicAdd(&cnt[k], 1);
    }
    __syncthreads();
    if (tid == 0) {
        int off = 0, nt = 0;
        for (int k = 0; k < K_ENS; k++) {
            cur[k] = off;
            int c = cnt[k];
            int member_start = nt;
            for (int s = 0; s < c; s += TM) {
                g_tileK[nt] = k;
                g_tileStart[nt] = off + s;
                g_tileRows[nt] = (c - s < TM) ? (c - s) : TM;
                nt++;
            }
            if ((nt - member_start) & 1) {       // even-pad per member
                g_tileK[nt] = k;
                g_tileStart[nt] = off;
                g_tileRows[nt] = 0;
                nt++;
            }
            off += c;
        }
        g_ntiles = nt;
        for (int e = nt; e < MAXTILES; e++) { g_tileRows[e] = 0; g_tileK[e] = 0; g_tileStart[e] = 0; }
    }
    __syncthreads();
    for (int b = tid; b < B_TOT; b += SETUP_THREADS) {
        int k = is_i32 ? assign_raw[b] : assign_raw[2 * b];
        int pos = atomicAdd(&cur[k], 1);
        g_perm[pos] = b;
    }
}

// ============================================================
// Prep: pack W into per-member kit-major chunk stream in g_ws.
// ============================================================
__device__ __forceinline__ uint32_t pack_hi(float v0, float v1) {
    __nv_bfloat162 p = __floats2bfloat162_rn(v0, v1);
    return *(uint32_t*)&p;
}
__device__ void pack_one(const float* __restrict__ W, unsigned char* __restrict__ ws,
                         int K, int N, int NP, size_t lbase, size_t cstride,
                         int km, int idx) {
    const int nkit = K / 16, ntile = NP / 8;
    const int total = ntile * nkit * 32;
    if (idx >= total) return;

    const int lane = idx & 31;
    const int kit  = (idx >> 5) % nkit;
    const int tile = (idx >> 5) / nkit;
    const int g = lane >> 2, t4 = lane & 3;
    const int n = tile * 8 + g;
    const int ka = kit * 16 + 2 * t4;
    const int kb = kit * 16 + 8 + 2 * t4;

    const float* Wm = W + (size_t)km * K * N;
    float va0 = (n < N) ? Wm[(size_t)ka * N + n] : 0.f;
    float va1 = (n < N) ? Wm[(size_t)(ka + 1) * N + n] : 0.f;
    float vb0 = (n < N) ? Wm[(size_t)kb * N + n] : 0.f;
    float vb1 = (n < N) ? Wm[(size_t)(kb + 1) * N + n] : 0.f;

    __nv_bfloat16 ha0 = __float2bfloat16(va0), ha1 = __float2bfloat16(va1);
    __nv_bfloat16 hb0 = __float2bfloat16(vb0), hb1 = __float2bfloat16(vb1);
    float la0 = va0 - __bfloat162float(ha0), la1 = va1 - __bfloat162float(ha1);
    float lb0 = vb0 - __bfloat162float(hb0), lb1 = vb1 - __bfloat162float(hb1);

    uint4 v;
    v.x = ((uint32_t)*(uint16_t*)&ha0) | ((uint32_t)*(uint16_t*)&ha1 << 16);
    v.y = ((uint32_t)*(uint16_t*)&hb0) | ((uint32_t)*(uint16_t*)&hb1 << 16);
    v.z = pack_hi(la0, la1);
    v.w = pack_hi(lb0, lb1);

    *(uint4*)(ws + (size_t)km * STREAM_BYTES + lbase +
              (size_t)kit * cstride + ((size_t)tile * 32 + lane) * 16) = v;
}
__global__ void pack_all(const float* __restrict__ W1,
                         const float* __restrict__ W2,
                         const float* __restrict__ W3,
                         unsigned char* __restrict__ ws) {
    const int km = blockIdx.z;
    const int idx = blockIdx.x * blockDim.x + threadIdx.x;
    if (blockIdx.y == 0)      pack_one(W1, ws, IN1, HID, HID,   0,       (size_t)NT1*32*16, km, idx);
    else if (blockIdx.y == 1) pack_one(W2, ws, HID, HID, HID,   L2_BASE, (size_t)NT1*32*16, km, idx);
    else                      pack_one(W3, ws, HID, OUTD, N3PAD, L3_BASE, (size_t)NT3*32*16, km, idx);
}

// ============================================================
// Helpers
// ============================================================
__device__ __forceinline__ float softplusf(float z) {
    return (z > 0.f) ? (z + log1pf(__expf(-z))) : log1pf(__expf(z));
}
__device__ __forceinline__ float swishf(float x) {
    return x * __frcp_rn(1.f + __expf(-x));
}
__device__ __forceinline__ void split_store(__nv_bfloat16* hh, __nv_bfloat16* hl,
                                            int idx, float v) {
    __nv_bfloat16 h = __float2bfloat16(v);
    hh[idx] = h;
    hl[idx] = __float2bfloat16(v - __bfloat162float(h));
}
__device__ __forceinline__ void hmma(float* c, const uint32_t* a,
                                     uint32_t b0, uint32_t b1) {
    asm("mma.sync.aligned.m16n8k16.row.col.f32.bf16.bf16.f32 "
        "{%0,%1,%2,%3}, {%4,%5,%6,%7}, {%8,%9}, {%0,%1,%2,%3};"
        : "+f"(c[0]), "+f"(c[1]), "+f"(c[2]), "+f"(c[3])
        : "r"(a[0]), "r"(a[1]), "r"(a[2]), "r"(a[3]), "r"(b0), "r"(b1));
}
__device__ __forceinline__ void ldsm_x4(uint32_t* a, uint32_t addr) {
    asm volatile("ldmatrix.sync.aligned.m8n8.x4.shared.b16 {%0,%1,%2,%3}, [%4];"
        : "=r"(a[0]), "=r"(a[1]), "=r"(a[2]), "=r"(a[3]) : "r"(addr));
}

// ============================================================
// Multicast weight pipeline state (per-thread copy; t0 acts)
// ============================================================
struct Pipe {
    uint32_t mb;              // 8 barriers: full[s]=mb+s*8, empty[s]=mb+32+s*8
    uint32_t ring;            // smem addr of ring base
    const unsigned char* wsrc;
    int tid, lane, prank, peer_active;
    int gi, ci, gc;           // issue index, chunk-in-step, consume index

    __device__ __forceinline__ uint32_t fullb(int s)  const { return mb + s * 8; }
    __device__ __forceinline__ uint32_t emptyb(int s) const { return mb + 32 + s * 8; }

    __device__ __forceinline__ void issue() {
        if (gi >= TOTAL_CHUNKS) return;
        const int s = gi & 3;
        if (tid == 0) {
            if (gi >= 4) { int u = gi >> 2; MBAR_WAIT_RLX(emptyb(s), (u - 1) & 1); }
            size_t off; unsigned bytes;
            if (ci < 5)       { off = (size_t)ci * (size_t)SLOT_BYTES;            bytes = 32768u; }
            else if (ci < 37) { off = L2_BASE + (size_t)(ci - 5) * 32768u;        bytes = 32768u; }
            else              { off = L3_BASE + (size_t)(ci - 37) * 8704u;        bytes = 8704u; }
            MBAR_EXPECT_TX(fullb(s), bytes);
            if (prank == 1) {   // I am rank 0 (prank = my_rank^1)
                uint32_t dst = ring + s * SLOT_BYTES;
                if (peer_active) CP_BULK_MC(dst, wsrc + off, bytes, fullb(s), 3);
                else             CP_BULK(dst, wsrc + off, bytes, fullb(s));
            }
        }
        gi++;
        ci++; if (ci == CHUNKS_PER_STEP) ci = 0;
    }
    __device__ __forceinline__ void cwait() {
        MBAR_WAIT_ACQ(fullb(gc & 3), (gc >> 2) & 1);
    }
    __device__ __forceinline__ void cdone() {
        __syncwarp();
        if (lane == 0) {
            MBAR_ARRIVE(emptyb(gc & 3));
            if (peer_active) ARRIVE_PEER(emptyb(gc & 3), prank);
        }
        gc++;
    }
};

// ============================================================
// Dense layer (layers 1 & 2): weights from multicast smem ring.
// ============================================================
template<int NKIT, int ASTR>
__device__ __forceinline__ void layer_dense(
    Pipe& p, char* smring,
    const __nv_bfloat16* Ah, const __nv_bfloat16* Al,
    const float* bias,
    __nv_bfloat16* Oh, __nv_bfloat16* Ol,
    int warp, int lane)
{
    const int t4 = lane & 3;
    const int g = lane >> 2;
    const int nbase = warp * 32;

    float acc[8][4];
#pragma unroll
    for (int i = 0; i < 8; i++)
#pragma unroll
        for (int j = 0; j < 4; j++) acc[i][j] = 0.f;

    const uint32_t aAh = smem_u32(Ah), aAl = smem_u32(Al);
    const int roff0 = (((lane & 15)) * ASTR + ((lane >> 4) * 8)) * 2;
    const int roff1 = (((lane & 15) + 16) * ASTR + ((lane >> 4) * 8)) * 2;

#pragma unroll 2
    for (int kit = 0; kit < NKIT; kit++) {
        p.cwait();
        const uint4* ws = (const uint4*)(smring + (size_t)(p.gc & 3) * SLOT_BYTES);
        uint4 bf[4];
#pragma unroll
        for (int nt = 0; nt < 4; nt++)
            bf[nt] = ws[(warp * 4 + nt) * 32 + lane];

        const int kb = kit * 32;
        uint32_t ah[2][4], al[2][4];
        ldsm_x4(ah[0], aAh + roff0 + kb);
        ldsm_x4(ah[1], aAh + roff1 + kb);
        ldsm_x4(al[0], aAl + roff0 + kb);
        ldsm_x4(al[1], aAl + roff1 + kb);

#pragma unroll
        for (int nt = 0; nt < 4; nt++)
#pragma unroll
            for (int mt = 0; mt < 2; mt++)
                hmma(acc[nt * 2 + mt], ah[mt], bf[nt].x, bf[nt].y);
#pragma unroll
        for (int nt = 0; nt < 4; nt++)
#pragma unroll
            for (int mt = 0; mt < 2; mt++)
                hmma(acc[nt * 2 + mt], al[mt], bf[nt].x, bf[nt].y);
#pragma unroll
        for (int nt = 0; nt < 4; nt++)
#pragma unroll
            for (int mt = 0; mt < 2; mt++)
                hmma(acc[nt * 2 + mt], ah[mt], bf[nt].z, bf[nt].w);

        p.issue();     // chunk gc+3 (3 primed) -> slot != current, deps on kit-1
        p.cdone();
    }
    __syncthreads();   // all activation reads done before overwrite
#pragma unroll
    for (int nt = 0; nt < 4; nt++)
#pragma unroll
        for (int mt = 0; mt < 2; mt++) {
            float* c = acc[nt * 2 + mt];
            const int c0 = nbase + nt * 8 + t4 * 2;
            const int r0 = mt * 16 + g;
            const float bv0 = bias[c0], bv1 = bias[c0 + 1];
            split_store(Oh, Ol, r0 * HS + c0,           swishf(c[0] + bv0));
            split_store(Oh, Ol, r0 * HS + c0 + 1,       swishf(c[1] + bv1));
            split_store(Oh, Ol, (r0 + 8) * HS + c0,     swishf(c[2] + bv0));
            split_store(Oh, Ol, (r0 + 8) * HS + c0 + 1, swishf(c[3] + bv1));
        }
}

// ============================================================
// Persistent rollout: cluster-2, multicast weight stream.
// ============================================================
__global__ void __launch_bounds__(NTHREADS) __cluster_dims__(2, 1, 1)
rollout_kernel(
    const float* __restrict__ obs,
    const float* __restrict__ acts,
    const float* __restrict__ b1, const float* __restrict__ b2,
    const float* __restrict__ b3,
    const float* __restrict__ maxlv, const float* __restrict__ minlv,
    const float* __restrict__ noise,
    const unsigned char* __restrict__ wstream,
    float* __restrict__ out_obs,
    float* __restrict__ out_rew)
{
    const int tile = blockIdx.x;
    const int nrows = g_tileRows[tile];
    if (nrows == 0) return;                       // pad CTA: no cluster ops, exit
    const int km    = g_tileK[tile];
    const int start = g_tileStart[tile];
    const int peer_active = (g_tileRows[tile ^ 1] > 0);

    extern __shared__ char sm[];
    __nv_bfloat16* Hh = (__nv_bfloat16*)(sm + OFF_HH);
    __nv_bfloat16* Hl = (__nv_bfloat16*)(sm + OFF_HL);
    __nv_bfloat16* Xh = (__nv_bfloat16*)(sm + OFF_XH);
    __nv_bfloat16* Xl = (__nv_bfloat16*)(sm + OFF_XL);
    float* sh_out = (float*)(sm + OFF_OUT);
    float* sb1 = (float*)(sm + OFF_B1);
    float* sb2 = (float*)(sm + OFF_B2);
    float* sb3 = (float*)(sm + OFF_B3);
    char*  smring = sm + OFF_RING;
    __shared__ int rows[TM];
    __shared__ __align__(8) unsigned long long mbar[8];

    const int tid  = threadIdx.x;
    const int warp = tid >> 5, lane = tid & 31;
    const int g = lane >> 2, t4 = lane & 3;
    const uint32_t rank = ctarank();

    Pipe p;
    p.mb = smem_u32(mbar);
    p.ring = smem_u32(smring);
    p.wsrc = wstream + (size_t)km * STREAM_BYTES;
    p.tid = tid; p.lane = lane;
    p.prank = (int)(rank ^ 1);
    p.peer_active = peer_active;
    p.gi = 0; p.ci = 0; p.gc = 0;

    if (tid < TM) rows[tid] = (tid < nrows) ? g_perm[start + tid] : 0;

    if (tid == 0) {
#pragma unroll
        for (int s = 0; s < RING; s++) {
            MBAR_INIT(p.fullb(s), 1);
            MBAR_INIT(p.emptyb(s), 16 * (1 + peer_active));
        }
    }

    for (int i = tid; i < HID; i += NTHREADS) {
        sb1[i] = b1[(size_t)km * HID + i];
        sb2[i] = b2[(size_t)km * HID + i];
    }
    for (int i = tid; i < N3PAD; i += NTHREADS)
        sb3[i] = (i < OUTD) ? b3[(size_t)km * OUTD + i] : 0.f;

    __syncthreads();                 // barriers + rows visible CTA-locally
    if (peer_active) CLUSTER_SYNC(); // peer barriers initialized before multicast

    // prime 3 chunks
    p.issue(); p.issue(); p.issue();

    // init activations
    for (int i = tid; i < TM * XS; i += NTHREADS) {
        Xh[i] = __float2bfloat16(0.f);
        Xl[i] = __float2bfloat16(0.f);
    }
    __syncthreads();
    for (int idx = tid; idx < TM * OBS; idx += NTHREADS) {
        int r = idx >> 6, d = idx & 63;
        float v = (r < nrows) ? obs[(size_t)rows[r] * OBS + d] : 0.f;
        split_store(Xh, Xl, r * XS + d, v);
    }

    for (int t = 0; t < T_STEPS; t++) {
        for (int idx = tid; idx < TM * ACT; idx += NTHREADS) {
            int r = idx >> 4, a = idx & 15;
            float v = (r < nrows) ? acts[((size_t)rows[r] * T_STEPS + t) * ACT + a] : 0.f;
            split_store(Xh, Xl, r * XS + OBS + a, v);
        }
        __syncthreads();

        layer_dense<NKIT1, XS>(p, smring, Xh, Xl, sb1, Hh, Hl, warp, lane);
        __syncthreads();
        layer_dense<NKIT2, HS>(p, smring, Hh, Hl, sb2, Hh, Hl, warp, lane);
        __syncthreads();

        // ===== layer 3 =====
        {
            float acc[2][2][4];
#pragma unroll
            for (int i = 0; i < 2; i++)
#pragma unroll
                for (int m = 0; m < 2; m++)
#pragma unroll
                    for (int j = 0; j < 4; j++) acc[i][m][j] = 0.f;
            const int ntiles = (warp == 0) ? 2 : 1;
            const int tn[2] = {warp, 16};

            const uint32_t aHh = smem_u32(Hh), aHl = smem_u32(Hl);
            const int roff0 = (((lane & 15)) * HS + ((lane >> 4) * 8)) * 2;
            const int roff1 = (((lane & 15) + 16) * HS + ((lane >> 4) * 8)) * 2;

#pragma unroll 2
            for (int kit = 0; kit < NKIT3; kit++) {
                p.cwait();
                const uint4* ws = (const uint4*)(smring + (size_t)(p.gc & 3) * SLOT_BYTES);
                uint4 bf[2];
                bf[0] = ws[tn[0] * 32 + lane];
                if (ntiles > 1) bf[1] = ws[tn[1] * 32 + lane];

                const int kb = kit * 32;
                uint32_t ah[2][4], al[2][4];
                ldsm_x4(ah[0], aHh + roff0 + kb);
                ldsm_x4(ah[1], aHh + roff1 + kb);
                ldsm_x4(al[0], aHl + roff0 + kb);
                ldsm_x4(al[1], aHl + roff1 + kb);

#pragma unroll
                for (int i = 0; i < 2; i++)
                    if (i < ntiles)
#pragma unroll
                        for (int mt = 0; mt < 2; mt++)
                            hmma(acc[i][mt], ah[mt], bf[i].x, bf[i].y);
#pragma unroll
                for (int i = 0; i < 2; i++)
                    if (i < ntiles)
#pragma unroll
                        for (int mt = 0; mt < 2; mt++)
                            hmma(acc[i][mt], al[mt], bf[i].x, bf[i].y);
#pragma unroll
                for (int i = 0; i < 2; i++)
                    if (i < ntiles)
#pragma unroll
                        for (int mt = 0; mt < 2; mt++)
                            hmma(acc[i][mt], ah[mt], bf[i].z, bf[i].w);

                p.issue();
                p.cdone();
            }
            __syncthreads();
            for (int i = 0; i < ntiles; i++) {
                const int c0 = tn[i] * 8 + t4 * 2;
#pragma unroll
                for (int mt = 0; mt < 2; mt++) {
                    float* c = acc[i][mt];
                    const int r0 = mt * 16 + g;
                    if (c0 < OUT_STRIDE) {
                        sh_out[r0 * OUT_STRIDE + c0]       = c[0] + sb3[c0];
                        sh_out[(r0 + 8) * OUT_STRIDE + c0] = c[2] + sb3[c0];
                    }
                    if (c0 + 1 < OUT_STRIDE) {
                        sh_out[r0 * OUT_STRIDE + c0 + 1]       = c[1] + sb3[c0 + 1];
                        sh_out[(r0 + 8) * OUT_STRIDE + c0 + 1] = c[3] + sb3[c0 + 1];
                    }
                }
            }
        }
        __syncthreads();

        // ===== postprocess =====
        const float* nz_t = noise + ((size_t)t * K_ENS + km) * B_TOT * OBS;
        for (int idx = tid; idx < TM * OBS; idx += NTHREADS) {
            int r = idx >> 6, d = idx & 63;
            if (r < nrows) {
                int row = rows[r];
                float mean = sh_out[r * OUT_STRIDE + d];
                float lv   = sh_out[r * OUT_STRIDE + OBS + d];
                float mx = __ldg(maxlv + d), mn = __ldg(minlv + d);
                lv = mx - softplusf(mx - lv);
                lv = mn + softplusf(lv - mn);
                float nz = __ldg(nz_t + (size_t)row * OBS + d);
                float no = fmaf(nz, __expf(0.5f * lv), mean);
                out_obs[((size_t)row * T_STEPS + t) * OBS + d] = no;
                split_store(Xh, Xl, r * XS + d, no);
            }
        }
        if (tid < nrows)
            out_rew[(size_t)rows[tid] * T_STEPS + t] = sh_out[tid * OUT_STRIDE + 128];
        __syncthreads();
    }

    if (peer_active) CLUSTER_SYNC();  // no early teardown under in-flight peer arrives
}

// ============================================================
// Launch
// ============================================================
extern "C" void kernel_launch(void* const* d_in, const int* in_sizes, int n_in,
                              void* d_out, int out_size) {
    const float* obs   = (const float*)d_in[0];
    const float* acts  = (const float*)d_in[1];
    const float* W1    = (const float*)d_in[2];
    const float* b1    = (const float*)d_in[3];
    const float* W2    = (const float*)d_in[4];
    const float* b2    = (const float*)d_in[5];
    const float* W3    = (const float*)d_in[6];
    const float* b3    = (const float*)d_in[7];
    const float* maxlv = (const float*)d_in[8];
    const float* minlv = (const float*)d_in[9];
    const float* noise = (const float*)d_in[10];
    const int*   assign_raw = (const int*)d_in[11];

    float* out_obs = (float*)d_out;
    float* out_rew = out_obs + (size_t)B_TOT * T_STEPS * OBS;

    unsigned char* ws;
    cudaGetSymbolAddress((void**)&ws, g_ws);

    cudaFuncSetAttribute(rollout_kernel,
                         cudaFuncAttributeMaxDynamicSharedMemorySize, SMEM_BYTES);

    setup_kernel<<<1, SETUP_THREADS>>>(assign_raw);

    {
        int maxtot = NT1 * NKIT2 * 32;   // 65536 (largest layer)
        pack_all<<<dim3((maxtot + 255) / 256, 3, K_ENS), 256>>>(W1, W2, W3, ws);
    }

    rollout_kernel<<<MAXTILES, NTHREADS, SMEM_BYTES>>>(
        obs, acts, b1, b2, b3, maxlv, minlv, noise, ws, out_obs, out_rew);
}

// round 16
// speedup vs baseline: 1.0008x; 1.0008x over previous
#include <cuda_runtime.h>
#include <cuda_bf16.h>
#include <math.h>
#include <stdint.h>

// Problem constants
#define B_TOT   4096
#define T_STEPS 25
#define K_ENS   8
#define OBS     64
#define ACT     16
#define IN1     80
#define HID     512
#define OUTD    129
#define N3PAD   136
#define TM      32
#define NTHREADS 512          // 16 warps
#define SETUP_THREADS 256
#define MAXTILES 144          // even-padded per member
#define OUT_STRIDE 132

// kit counts
#define NKIT1   (IN1/16)      // 5
#define NKIT2   (HID/16)      // 32
#define NKIT3   (HID/16)      // 32
#define NT1     (HID/8)       // 64 n8-tiles
#define NT3     (N3PAD/8)     // 17

// weight stream (per member, kit-major chunks)
#define L1_BYTES   (NKIT1*NT1*32*16)                 // 163840
#define L2_BYTES   (NKIT2*NT1*32*16)                 // 1048576
#define L3_BYTES   (NKIT3*NT3*32*16)                 // 278528
#define L2_BASE    L1_BYTES
#define L3_BASE    (L1_BYTES + L2_BYTES)             // 1212416
#define STREAM_BYTES (L1_BYTES + L2_BYTES + L3_BYTES) // 1490944
#define CHUNKS_PER_STEP 69
#define TOTAL_CHUNKS (T_STEPS * CHUNKS_PER_STEP)     // 1725

// ring
#define RING 4
#define SLOT_BYTES 32768

// activation smem strides (bf16 elems)
#define XS      88
#define HS      520

// dynamic smem layout (bytes)
#define OFF_HH   0
#define OFF_HL   (OFF_HH + TM*HS*2)
#define OFF_XH   (OFF_HL + TM*HS*2)
#define OFF_XL   (OFF_XH + TM*XS*2)
#define OFF_OUT  (OFF_XL + TM*XS*2)
#define OFF_B1   (OFF_OUT + TM*OUT_STRIDE*4)
#define OFF_B2   (OFF_B1 + HID*4)
#define OFF_B3   (OFF_B2 + HID*4)
#define OFF_RING (((OFF_B3 + N3PAD*4) + 1023) & ~1023)
#define SMEM_BYTES (OFF_RING + RING*SLOT_BYTES)

// ---- device-global scratch ----
__device__ int g_perm[B_TOT];
__device__ int g_tileK[MAXTILES];
__device__ int g_tileStart[MAXTILES];
__device__ int g_tileRows[MAXTILES];
__device__ int g_ntiles;

__device__ __align__(16) unsigned char g_ws[(size_t)K_ENS * STREAM_BYTES];

// ---- mbarrier / bulk-async PTX ----
#define MBAR_INIT(addr, cnt) \
    asm volatile("mbarrier.init.shared.b64 [%0], %1;" :: "r"(addr), "r"(cnt) : "memory")
#define MBAR_EXPECT_TX(addr, bytes) \
    asm volatile("mbarrier.arrive.expect_tx.shared.b64 _, [%0], %1;" :: "r"(addr), "r"(bytes) : "memory")
#define MBAR_ARRIVE(addr) \
    asm volatile("mbarrier.arrive.shared.b64 _, [%0];" :: "r"(addr) : "memory")
#define ARRIVE_PEER(addr, prank) \
    asm volatile("{\n\t.reg .b32 r;\n\tmapa.shared::cluster.u32 r, %0, %1;\n\t" \
                 "mbarrier.arrive.shared::cluster.b64 _, [r];\n\t}" \
                 :: "r"(addr), "r"(prank) : "memory")
#define MBAR_WAIT_ACQ(addr, ph) do { unsigned _done = 0; \
    while (!_done) { \
        asm volatile("{\n\t.reg .pred p;\n\t" \
            "mbarrier.try_wait.parity.acquire.cta.shared::cta.b64 p, [%1], %2, 0x989680;\n\t" \
            "selp.b32 %0, 1, 0, p;\n\t}" \
            : "=r"(_done) : "r"(addr), "r"((unsigned)(ph)) : "memory"); \
    } } while (0)
#define MBAR_WAIT_RLX(addr, ph) do { unsigned _done = 0; \
    while (!_done) { \
        asm volatile("{\n\t.reg .pred p;\n\t" \
            "mbarrier.try_wait.parity.relaxed.cta.shared::cta.b64 p, [%1], %2, 0x989680;\n\t" \
            "selp.b32 %0, 1, 0, p;\n\t}" \
            : "=r"(_done) : "r"(addr), "r"((unsigned)(ph)) : "memory"); \
    } } while (0)
#define CP_BULK(dst, src, bytes, mbar) \
    asm volatile("cp.async.bulk.shared::cluster.global.mbarrier::complete_tx::bytes [%0], [%1], %2, [%3];" \
        :: "r"(dst), "l"(src), "r"(bytes), "r"(mbar) : "memory")
#define CP_BULK_MC(dst, src, bytes, mbar, mask) \
    asm volatile("cp.async.bulk.shared::cluster.global.mbarrier::complete_tx::bytes.multicast::cluster [%0], [%1], %2, [%3], %4;" \
        :: "r"(dst), "l"(src), "r"(bytes), "r"(mbar), "h"((uint16_t)(mask)) : "memory")
#define CLUSTER_SYNC() do { \
    asm volatile("barrier.cluster.arrive.aligned;" ::: "memory"); \
    asm volatile("barrier.cluster.wait.aligned;" ::: "memory"); } while (0)

__device__ __forceinline__ uint32_t smem_u32(const void* p) {
    uint32_t a;
    asm("{ .reg .u64 t; cvta.to.shared.u64 t, %1; cvt.u32.u64 %0, t; }" : "=r"(a) : "l"(p));
    return a;
}
__device__ __forceinline__ uint32_t ctarank() {
    uint32_t r; asm("mov.u32 %0, %%cluster_ctarank;" : "=r"(r)); return r;
}

// ============================================================
// Setup: dtype-detect + counting sort; tiles even-padded per member.
// ============================================================
__global__ void setup_kernel(const int* __restrict__ assign_raw) {
    __shared__ int cnt[K_ENS];
    __shared__ int cur[K_ENS];
    __shared__ int odd_nonzero;
    int tid = threadIdx.x;
    if (tid < K_ENS) cnt[tid] = 0;
    if (tid == 0) odd_nonzero = 0;
    __syncthreads();

    int local_nz = 0;
    for (int w = 2 * tid + 1; w < B_TOT; w += 2 * SETUP_THREADS)
        if (assign_raw[w] != 0) local_nz = 1;
    if (local_nz) atomicOr(&odd_nonzero, 1);
    __syncthreads();
    const bool is_i32 = (odd_nonzero != 0);

    for (int b = tid; b < B_TOT; b += SETUP_THREADS) {
        int k = is_i32 ? assign_raw[b] : assign_raw[2 * b];
        atomicAdd(&cnt[k], 1);
    }
    __syncthreads();
    if (tid == 0) {
        int off = 0, nt = 0;
        for (int k = 0; k < K_ENS; k++) {
            cur[k] = off;
            int c = cnt[k];
            int member_start = nt;
            for (int s = 0; s < c; s += TM) {
                g_tileK[nt] = k;
                g_tileStart[nt] = off + s;
                g_tileRows[nt] = (c - s < TM) ? (c - s) : TM;
                nt++;
            }
            if ((nt - member_start) & 1) {       // even-pad per member
                g_tileK[nt] = k;
                g_tileStart[nt] = off;
                g_tileRows[nt] = 0;
                nt++;
            }
            off += c;
        }
        g_ntiles = nt;
        for (int e = nt; e < MAXTILES; e++) { g_tileRows[e] = 0; g_tileK[e] = 0; g_tileStart[e] = 0; }
    }
    __syncthreads();
    for (int b = tid; b < B_TOT; b += SETUP_THREADS) {
        int k = is_i32 ? assign_raw[b] : assign_raw[2 * b];
        int pos = atomicAdd(&cur[k], 1);
        g_perm[pos] = b;
    }
}

// ============================================================
// Prep: pack W into per-member kit-major chunk stream in g_ws.
// ============================================================
__device__ __forceinline__ uint32_t pack_hi(float v0, float v1) {
    __nv_bfloat162 p = __floats2bfloat162_rn(v0, v1);
    return *(uint32_t*)&p;
}
__device__ void pack_one(const float* __restrict__ W, unsigned char* __restrict__ ws,
                         int K, int N, int NP, size_t lbase, size_t cstride,
                         int km, int idx) {
    const int nkit = K / 16, ntile = NP / 8;
    const int total = ntile * nkit * 32;
    if (idx >= total) return;

    const int lane = idx & 31;
    const int kit  = (idx >> 5) % nkit;
    const int tile = (idx >> 5) / nkit;
    const int g = lane >> 2, t4 = lane & 3;
    const int n = tile * 8 + g;
    const int ka = kit * 16 + 2 * t4;
    const int kb = kit * 16 + 8 + 2 * t4;

    const float* Wm = W + (size_t)km * K * N;
    float va0 = (n < N) ? Wm[(size_t)ka * N + n] : 0.f;
    float va1 = (n < N) ? Wm[(size_t)(ka + 1) * N + n] : 0.f;
    float vb0 = (n < N) ? Wm[(size_t)kb * N + n] : 0.f;
    float vb1 = (n < N) ? Wm[(size_t)(kb + 1) * N + n] : 0.f;

    __nv_bfloat16 ha0 = __float2bfloat16(va0), ha1 = __float2bfloat16(va1);
    __nv_bfloat16 hb0 = __float2bfloat16(vb0), hb1 = __float2bfloat16(vb1);
    float la0 = va0 - __bfloat162float(ha0), la1 = va1 - __bfloat162float(ha1);
    float lb0 = vb0 - __bfloat162float(hb0), lb1 = vb1 - __bfloat162float(hb1);

    uint4 v;
    v.x = ((uint32_t)*(uint16_t*)&ha0) | ((uint32_t)*(uint16_t*)&ha1 << 16);
    v.y = ((uint32_t)*(uint16_t*)&hb0) | ((uint32_t)*(uint16_t*)&hb1 << 16);
    v.z = pack_hi(la0, la1);
    v.w = pack_hi(lb0, lb1);

    *(uint4*)(ws + (size_t)km * STREAM_BYTES + lbase +
              (size_t)kit * cstride + ((size_t)tile * 32 + lane) * 16) = v;
}
__global__ void pack_all(const float* __restrict__ W1,
                         const float* __restrict__ W2,
                         const float* __restrict__ W3,
                         unsigned char* __restrict__ ws) {
    const int km = blockIdx.z;
    const int idx = blockIdx.x * blockDim.x + threadIdx.x;
    if (blockIdx.y == 0)      pack_one(W1, ws, IN1, HID, HID,   0,       (size_t)NT1*32*16, km, idx);
    else if (blockIdx.y == 1) pack_one(W2, ws, HID, HID, HID,   L2_BASE, (size_t)NT1*32*16, km, idx);
    else                      pack_one(W3, ws, HID, OUTD, N3PAD, L3_BASE, (size_t)NT3*32*16, km, idx);
}

// ============================================================
// Helpers
// ============================================================
__device__ __forceinline__ float softplusf(float z) {
    return (z > 0.f) ? (z + log1pf(__expf(-z))) : log1pf(__expf(z));
}
__device__ __forceinline__ float swishf(float x) {
    return x * __frcp_rn(1.f + __expf(-x));
}
__device__ __forceinline__ void split_store(__nv_bfloat16* hh, __nv_bfloat16* hl,
                                            int idx, float v) {
    __nv_bfloat16 h = __float2bfloat16(v);
    hh[idx] = h;
    hl[idx] = __float2bfloat16(v - __bfloat162float(h));
}
__device__ __forceinline__ void hmma(float* c, const uint32_t* a,
                                     uint32_t b0, uint32_t b1) {
    asm("mma.sync.aligned.m16n8k16.row.col.f32.bf16.bf16.f32 "
        "{%0,%1,%2,%3}, {%4,%5,%6,%7}, {%8,%9}, {%0,%1,%2,%3};"
        : "+f"(c[0]), "+f"(c[1]), "+f"(c[2]), "+f"(c[3])
        : "r"(a[0]), "r"(a[1]), "r"(a[2]), "r"(a[3]), "r"(b0), "r"(b1));
}
__device__ __forceinline__ void ldsm_x4(uint32_t* a, uint32_t addr) {
    asm volatile("ldmatrix.sync.aligned.m8n8.x4.shared.b16 {%0,%1,%2,%3}, [%4];"
        : "=r"(a[0]), "=r"(a[1]), "=r"(a[2]), "=r"(a[3]) : "r"(addr));
}

// ============================================================
// Multicast weight pipeline state (per-thread copy; t0 acts)
// ============================================================
struct Pipe {
    uint32_t mb;              // 8 barriers: full[s]=mb+s*8, empty[s]=mb+32+s*8
    uint32_t ring;            // smem addr of ring base
    const unsigned char* wsrc;
    int tid, lane, prank, peer_active;
    int gi, ci, gc;           // issue index, chunk-in-step, consume index

    __device__ __forceinline__ uint32_t fullb(int s)  const { return mb + s * 8; }
    __device__ __forceinline__ uint32_t emptyb(int s) const { return mb + 32 + s * 8; }

    __device__ __forceinline__ void issue() {
        if (gi >= TOTAL_CHUNKS) return;
        const int s = gi & 3;
        if (tid == 0) {
            if (gi >= 4) { int u = gi >> 2; MBAR_WAIT_RLX(emptyb(s), (u - 1) & 1); }
            size_t off; unsigned bytes;
            if (ci < 5)       { off = (size_t)ci * (size_t)SLOT_BYTES;            bytes = 32768u; }
            else if (ci < 37) { off = L2_BASE + (size_t)(ci - 5) * 32768u;        bytes = 32768u; }
            else              { off = L3_BASE + (size_t)(ci - 37) * 8704u;        bytes = 8704u; }
            MBAR_EXPECT_TX(fullb(s), bytes);
            if (prank == 1) {   // I am rank 0 (prank = my_rank^1)
                uint32_t dst = ring + s * SLOT_BYTES;
                if (peer_active) CP_BULK_MC(dst, wsrc + off, bytes, fullb(s), 3);
                else             CP_BULK(dst, wsrc + off, bytes, fullb(s));
            }
        }
        gi++;
        ci++; if (ci == CHUNKS_PER_STEP) ci = 0;
    }
    __device__ __forceinline__ void cwait() {
        MBAR_WAIT_ACQ(fullb(gc & 3), (gc >> 2) & 1);
    }
    __device__ __forceinline__ void cdone() {
        __syncwarp();
        if (lane == 0) {
            MBAR_ARRIVE(emptyb(gc & 3));
            if (peer_active) ARRIVE_PEER(emptyb(gc & 3), prank);
        }
        gc++;
    }
};

// ============================================================
// Dense layer (layers 1 & 2): weights from multicast smem ring.
// ============================================================
template<int NKIT, int ASTR>
__device__ __forceinline__ void layer_dense(
    Pipe& p, char* smring,
    const __nv_bfloat16* Ah, const __nv_bfloat16* Al,
    const float* bias,
    __nv_bfloat16* Oh, __nv_bfloat16* Ol,
    int warp, int lane)
{
    const int t4 = lane & 3;
    const int g = lane >> 2;
    const int nbase = warp * 32;

    float acc[8][4];
#pragma unroll
    for (int i = 0; i < 8; i++)
#pragma unroll
        for (int j = 0; j < 4; j++) acc[i][j] = 0.f;

    const uint32_t aAh = smem_u32(Ah), aAl = smem_u32(Al);
    const int roff0 = (((lane & 15)) * ASTR + ((lane >> 4) * 8)) * 2;
    const int roff1 = (((lane & 15) + 16) * ASTR + ((lane >> 4) * 8)) * 2;

#pragma unroll 2
    for (int kit = 0; kit < NKIT; kit++) {
        p.cwait();
        const uint4* ws = (const uint4*)(smring + (size_t)(p.gc & 3) * SLOT_BYTES);
        uint4 bf[4];
#pragma unroll
        for (int nt = 0; nt < 4; nt++)
            bf[nt] = ws[(warp * 4 + nt) * 32 + lane];

        const int kb = kit * 32;
        uint32_t ah[2][4], al[2][4];
        ldsm_x4(ah[0], aAh + roff0 + kb);
        ldsm_x4(ah[1], aAh + roff1 + kb);
        ldsm_x4(al[0], aAl + roff0 + kb);
        ldsm_x4(al[1], aAl + roff1 + kb);

#pragma unroll
        for (int nt = 0; nt < 4; nt++)
#pragma unroll
            for (int mt = 0; mt < 2; mt++)
                hmma(acc[nt * 2 + mt], ah[mt], bf[nt].x, bf[nt].y);
#pragma unroll
        for (int nt = 0; nt < 4; nt++)
#pragma unroll
            for (int mt = 0; mt < 2; mt++)
                hmma(acc[nt * 2 + mt], al[mt], bf[nt].x, bf[nt].y);
#pragma unroll
        for (int nt = 0; nt < 4; nt++)
#pragma unroll
            for (int mt = 0; mt < 2; mt++)
                hmma(acc[nt * 2 + mt], ah[mt], bf[nt].z, bf[nt].w);

        p.issue();     // chunk gc+3 (3 primed) -> slot != current, deps on kit-1
        p.cdone();
    }
    __syncthreads();   // all activation reads done before overwrite
#pragma unroll
    for (int nt = 0; nt < 4; nt++)
#pragma unroll
        for (int mt = 0; mt < 2; mt++) {
            float* c = acc[nt * 2 + mt];
            const int c0 = nbase + nt * 8 + t4 * 2;
            const int r0 = mt * 16 + g;
            const float bv0 = bias[c0], bv1 = bias[c0 + 1];
            split_store(Oh, Ol, r0 * HS + c0,           swishf(c[0] + bv0));
            split_store(Oh, Ol, r0 * HS + c0 + 1,       swishf(c[1] + bv1));
            split_store(Oh, Ol, (r0 + 8) * HS + c0,     swishf(c[2] + bv0));
            split_store(Oh, Ol, (r0 + 8) * HS + c0 + 1, swishf(c[3] + bv1));
        }
}

// ============================================================
// Persistent rollout: cluster-2, multicast weight stream.
// ============================================================
__global__ void __launch_bounds__(NTHREADS) __cluster_dims__(2, 1, 1)
rollout_kernel(
    const float* __restrict__ obs,
    const float* __restrict__ acts,
    const float* __restrict__ b1, const float* __restrict__ b2,
    const float* __restrict__ b3,
    const float* __restrict__ maxlv, const float* __restrict__ minlv,
    const float* __restrict__ noise,
    const unsigned char* __restrict__ wstream,
    float* __restrict__ out_obs,
    float* __restrict__ out_rew)
{
    const int tile = blockIdx.x;
    const int nrows = g_tileRows[tile];
    if (nrows == 0) return;                       // pad CTA: no cluster ops, exit
    const int km    = g_tileK[tile];
    const int start = g_tileStart[tile];
    const int peer_active = (g_tileRows[tile ^ 1] > 0);

    extern __shared__ char sm[];
    __nv_bfloat16* Hh = (__nv_bfloat16*)(sm + OFF_HH);
    __nv_bfloat16* Hl = (__nv_bfloat16*)(sm + OFF_HL);
    __nv_bfloat16* Xh = (__nv_bfloat16*)(sm + OFF_XH);
    __nv_bfloat16* Xl = (__nv_bfloat16*)(sm + OFF_XL);
    float* sh_out = (float*)(sm + OFF_OUT);
    float* sb1 = (float*)(sm + OFF_B1);
    float* sb2 = (float*)(sm + OFF_B2);
    float* sb3 = (float*)(sm + OFF_B3);
    char*  smring = sm + OFF_RING;
    __shared__ int rows[TM];
    __shared__ __align__(8) unsigned long long mbar[8];

    const int tid  = threadIdx.x;
    const int warp = tid >> 5, lane = tid & 31;
    const int g = lane >> 2, t4 = lane & 3;
    const uint32_t rank = ctarank();

    Pipe p;
    p.mb = smem_u32(mbar);
    p.ring = smem_u32(smring);
    p.wsrc = wstream + (size_t)km * STREAM_BYTES;
    p.tid = tid; p.lane = lane;
    p.prank = (int)(rank ^ 1);
    p.peer_active = peer_active;
    p.gi = 0; p.ci = 0; p.gc = 0;

    if (tid < TM) rows[tid] = (tid < nrows) ? g_perm[start + tid] : 0;

    if (tid == 0) {
#pragma unroll
        for (int s = 0; s < RING; s++) {
            MBAR_INIT(p.fullb(s), 1);
            MBAR_INIT(p.emptyb(s), 16 * (1 + peer_active));
        }
    }

    for (int i = tid; i < HID; i += NTHREADS) {
        sb1[i] = b1[(size_t)km * HID + i];
        sb2[i] = b2[(size_t)km * HID + i];
    }
    for (int i = tid; i < N3PAD; i += NTHREADS)
        sb3[i] = (i < OUTD) ? b3[(size_t)km * OUTD + i] : 0.f;

    __syncthreads();                 // barriers + rows visible CTA-locally
    if (peer_active) CLUSTER_SYNC(); // peer barriers initialized before multicast

    // prime 3 chunks
    p.issue(); p.issue(); p.issue();

    // init activations
    for (int i = tid; i < TM * XS; i += NTHREADS) {
        Xh[i] = __float2bfloat16(0.f);
        Xl[i] = __float2bfloat16(0.f);
    }
    __syncthreads();
    for (int idx = tid; idx < TM * OBS; idx += NTHREADS) {
        int r = idx >> 6, d = idx & 63;
        float v = (r < nrows) ? obs[(size_t)rows[r] * OBS + d] : 0.f;
        split_store(Xh, Xl, r * XS + d, v);
    }

    for (int t = 0; t < T_STEPS; t++) {
        for (int idx = tid; idx < TM * ACT; idx += NTHREADS) {
            int r = idx >> 4, a = idx & 15;
            float v = (r < nrows) ? acts[((size_t)rows[r] * T_STEPS + t) * ACT + a] : 0.f;
            split_store(Xh, Xl, r * XS + OBS + a, v);
        }
        __syncthreads();

        layer_dense<NKIT1, XS>(p, smring, Xh, Xl, sb1, Hh, Hl, warp, lane);
        __syncthreads();
        layer_dense<NKIT2, HS>(p, smring, Hh, Hl, sb2, Hh, Hl, warp, lane);
        __syncthreads();

        // ===== layer 3 =====
        {
            float acc[2][2][4];
#pragma unroll
            for (int i = 0; i < 2; i++)
#pragma unroll
                for (int m = 0; m < 2; m++)
#pragma unroll
                    for (int j = 0; j < 4; j++) acc[i][m][j] = 0.f;
            const int ntiles = (warp == 0) ? 2 : 1;
            const int tn[2] = {warp, 16};

            const uint32_t aHh = smem_u32(Hh), aHl = smem_u32(Hl);
            const int roff0 = (((lane & 15)) * HS + ((lane >> 4) * 8)) * 2;
            const int roff1 = (((lane & 15) + 16) * HS + ((lane >> 4) * 8)) * 2;

#pragma unroll 2
            for (int kit = 0; kit < NKIT3; kit++) {
                p.cwait();
                const uint4* ws = (const uint4*)(smring + (size_t)(p.gc & 3) * SLOT_BYTES);
                uint4 bf[2];
                bf[0] = ws[tn[0] * 32 + lane];
                if (ntiles > 1) bf[1] = ws[tn[1] * 32 + lane];

                const int kb = kit * 32;
                uint32_t ah[2][4], al[2][4];
                ldsm_x4(ah[0], aHh + roff0 + kb);
                ldsm_x4(ah[1], aHh + roff1 + kb);
                ldsm_x4(al[0], aHl + roff0 + kb);
                ldsm_x4(al[1], aHl + roff1 + kb);

#pragma unroll
                for (int i = 0; i < 2; i++)
                    if (i < ntiles)
#pragma unroll
                        for (int mt = 0; mt < 2; mt++)
                            hmma(acc[i][mt], ah[mt], bf[i].x, bf[i].y);
#pragma unroll
                for (int i = 0; i < 2; i++)
                    if (i < ntiles)
#pragma unroll
                        for (int mt = 0; mt < 2; mt++)
                            hmma(acc[i][mt], al[mt], bf[i].x, bf[i].y);
#pragma unroll
                for (int i = 0; i < 2; i++)
                    if (i < ntiles)
#pragma unroll
                        for (int mt = 0; mt < 2; mt++)
                            hmma(acc[i][mt], ah[mt], bf[i].z, bf[i].w);

                p.issue();
                p.cdone();
            }
            __syncthreads();
            for (int i = 0; i < ntiles; i++) {
                const int c0 = tn[i] * 8 + t4 * 2;
#pragma unroll
                for (int mt = 0; mt < 2; mt++) {
                    float* c = acc[i][mt];
                    const int r0 = mt * 16 + g;
                    if (c0 < OUT_STRIDE) {
                        sh_out[r0 * OUT_STRIDE + c0]       = c[0] + sb3[c0];
                        sh_out[(r0 + 8) * OUT_STRIDE + c0] = c[2] + sb3[c0];
                    }
                    if (c0 + 1 < OUT_STRIDE) {
                        sh_out[r0 * OUT_STRIDE + c0 + 1]       = c[1] + sb3[c0 + 1];
                        sh_out[(r0 + 8) * OUT_STRIDE + c0 + 1] = c[3] + sb3[c0 + 1];
                    }
                }
            }
        }
        __syncthreads();

        // ===== postprocess =====
        const float* nz_t = noise + ((size_t)t * K_ENS + km) * B_TOT * OBS;
        for (int idx = tid; idx < TM * OBS; idx += NTHREADS) {
            int r = idx >> 6, d = idx & 63;
            if (r < nrows) {
                int row = rows[r];
                float mean = sh_out[r * OUT_STRIDE + d];
                float lv   = sh_out[r * OUT_STRIDE + OBS + d];
                float mx = __ldg(maxlv + d), mn = __ldg(minlv + d);
                lv = mx - softplusf(mx - lv);
                lv = mn + softplusf(lv - mn);
                float nz = __ldg(nz_t + (size_t)row * OBS + d);
                float no = fmaf(nz, __expf(0.5f * lv), mean);
                out_obs[((size_t)row * T_STEPS + t) * OBS + d] = no;
                split_store(Xh, Xl, r * XS + d, no);
            }
        }
        if (tid < nrows)
            out_rew[(size_t)rows[tid] * T_STEPS + t] = sh_out[tid * OUT_STRIDE + 128];
        __syncthreads();
    }

    if (peer_active) CLUSTER_SYNC();  // no early teardown under in-flight peer arrives
}

// ============================================================
// Launch
// ============================================================
extern "C" void kernel_launch(void* const* d_in, const int* in_sizes, int n_in,
                              void* d_out, int out_size) {
    const float* obs   = (const float*)d_in[0];
    const float* acts  = (const float*)d_in[1];
    const float* W1    = (const float*)d_in[2];
    const float* b1    = (const float*)d_in[3];
    const float* W2    = (const float*)d_in[4];
    const float* b2    = (const float*)d_in[5];
    const float* W3    = (const float*)d_in[6];
    const float* b3    = (const float*)d_in[7];
    const float* maxlv = (const float*)d_in[8];
    const float* minlv = (const float*)d_in[9];
    const float* noise = (const float*)d_in[10];
    const int*   assign_raw = (const int*)d_in[11];

    float* out_obs = (float*)d_out;
    float* out_rew = out_obs + (size_t)B_TOT * T_STEPS * OBS;

    unsigned char* ws;
    cudaGetSymbolAddress((void**)&ws, g_ws);

    cudaFuncSetAttribute(rollout_kernel,
                         cudaFuncAttributeMaxDynamicSharedMemorySize, SMEM_BYTES);

    setup_kernel<<<1, SETUP_THREADS>>>(assign_raw);

    {
        int maxtot = NT1 * NKIT2 * 32;   // 65536 (largest layer)
        pack_all<<<dim3((maxtot + 255) / 256, 3, K_ENS), 256>>>(W1, W2, W3, ws);
    }

    rollout_kernel<<<MAXTILES, NTHREADS, SMEM_BYTES>>>(
        obs, acts, b1, b2, b3, maxlv, minlv, noise, ws, out_obs, out_rew);
}

// round 17
// speedup vs baseline: 1.6368x; 1.6355x over previous
#include <cuda_runtime.h>
#include <cuda_fp16.h>
#include <math.h>
#include <stdint.h>

// Problem constants
#define B_TOT   4096
#define T_STEPS 25
#define K_ENS   8
#define OBS     64
#define ACT     16
#define IN1     80
#define HID     512
#define OUTD    129
#define N3PAD   136
#define TM      32
#define NTHREADS 512          // 16 warps
#define SETUP_THREADS 256
#define MAXTILES 136
#define OUT_STRIDE 132

// kit counts
#define NKIT1   (IN1/16)      // 5
#define NKIT2   (HID/16)      // 32
#define NKIT3   (HID/16)      // 32
#define NT1     (HID/8)       // 64 n8-tiles
#define NT3     (N3PAD/8)     // 17

// activation smem strides (fp16 elems)
#define XS      88
#define HS      520

// dynamic smem layout (bytes)
#define OFF_HH   0
#define OFF_HL   (OFF_HH + TM*HS*2)
#define OFF_XH   (OFF_HL + TM*HS*2)
#define OFF_XL   (OFF_XH + TM*XS*2)
#define OFF_OUT  (OFF_XL + TM*XS*2)
#define OFF_B1   (OFF_OUT + TM*OUT_STRIDE*4)
#define OFF_B2   (OFF_B1 + HID*4)
#define OFF_B3   (OFF_B2 + HID*4)
#define SMEM_BYTES (OFF_B3 + N3PAD*4)

// ---- device-global scratch ----
__device__ int g_perm[B_TOT];
__device__ int g_tileK[MAXTILES];
__device__ int g_tileStart[MAXTILES];
__device__ int g_tileRows[MAXTILES];
__device__ int g_ntiles;

// fragment-packed fp16 weights: [km][n8][kit][lane] -> {b0,b1}
__device__ uint2 g_wp1[K_ENS * NT1 * NKIT1 * 32];
__device__ uint2 g_wp2[K_ENS * NT1 * NKIT2 * 32];
__device__ uint2 g_wp3[K_ENS * NT3 * NKIT3 * 32];

// ============================================================
// Setup kernel
// ============================================================
__global__ void setup_kernel(const int* __restrict__ assign_raw) {
    __shared__ int cnt[K_ENS];
    __shared__ int cur[K_ENS];
    __shared__ int odd_nonzero;
    int tid = threadIdx.x;
    if (tid < K_ENS) cnt[tid] = 0;
    if (tid == 0) odd_nonzero = 0;
    __syncthreads();

    int local_nz = 0;
    for (int w = 2 * tid + 1; w < B_TOT; w += 2 * SETUP_THREADS)
        if (assign_raw[w] != 0) local_nz = 1;
    if (local_nz) atomicOr(&odd_nonzero, 1);
    __syncthreads();
    const bool is_i32 = (odd_nonzero != 0);

    for (int b = tid; b < B_TOT; b += SETUP_THREADS) {
        int k = is_i32 ? assign_raw[b] : assign_raw[2 * b];
        atomicAdd(&cnt[k], 1);
    }
    __syncthreads();
    if (tid == 0) {
        int off = 0, nt = 0;
        for (int k = 0; k < K_ENS; k++) {
            cur[k] = off;
            int c = cnt[k];
            for (int s = 0; s < c; s += TM) {
                g_tileK[nt] = k;
                g_tileStart[nt] = off + s;
                g_tileRows[nt] = (c - s < TM) ? (c - s) : TM;
                nt++;
            }
            off += c;
        }
        g_ntiles = nt;
        for (int e = nt; e < MAXTILES; e++) g_tileRows[e] = 0;
    }
    __syncthreads();
    for (int b = tid; b < B_TOT; b += SETUP_THREADS) {
        int k = is_i32 ? assign_raw[b] : assign_raw[2 * b];
        int pos = atomicAdd(&cur[k], 1);
        g_perm[pos] = b;
    }
}

// ============================================================
// Prep (single launch): pack W into fp16 fragment layout.
// ============================================================
__device__ __forceinline__ uint32_t pack_h2(float v0, float v1) {
    __half2 p = __halves2half2(__float2half_rn(v0), __float2half_rn(v1));
    return *(uint32_t*)&p;
}
__device__ void pack_one(const float* __restrict__ W, uint2* __restrict__ out,
                         int K, int N, int NP, int km, int idx) {
    const int nkit = K / 16, ntile = NP / 8;
    const int total = ntile * nkit * 32;
    if (idx >= total) return;

    const int lane = idx & 31;
    const int kit  = (idx >> 5) % nkit;
    const int tile = (idx >> 5) / nkit;
    const int g = lane >> 2, t4 = lane & 3;
    const int n = tile * 8 + g;
    const int ka = kit * 16 + 2 * t4;
    const int kb = kit * 16 + 8 + 2 * t4;

    const float* Wm = W + (size_t)km * K * N;
    float va0 = (n < N) ? Wm[(size_t)ka * N + n] : 0.f;
    float va1 = (n < N) ? Wm[(size_t)(ka + 1) * N + n] : 0.f;
    float vb0 = (n < N) ? Wm[(size_t)kb * N + n] : 0.f;
    float vb1 = (n < N) ? Wm[(size_t)(kb + 1) * N + n] : 0.f;

    uint2 v;
    v.x = pack_h2(va0, va1);
    v.y = pack_h2(vb0, vb1);
    out[(size_t)km * total + ((size_t)tile * nkit + kit) * 32 + lane] = v;
}
__global__ void pack_all(const float* __restrict__ W1,
                         const float* __restrict__ W2,
                         const float* __restrict__ W3,
                         uint2* __restrict__ o1,
                         uint2* __restrict__ o2,
                         uint2* __restrict__ o3) {
    const int km = blockIdx.z;
    const int idx = blockIdx.x * blockDim.x + threadIdx.x;
    if (blockIdx.y == 0)      pack_one(W1, o1, IN1, HID, HID,   km, idx);
    else if (blockIdx.y == 1) pack_one(W2, o2, HID, HID, HID,   km, idx);
    else                      pack_one(W3, o3, HID, OUTD, N3PAD, km, idx);
}

// ============================================================
// Helpers
// ============================================================
__device__ __forceinline__ float softplusf(float z) {
    return (z > 0.f) ? (z + log1pf(__expf(-z))) : log1pf(__expf(z));
}
__device__ __forceinline__ float swishf(float x) {
    return x * __frcp_rn(1.f + __expf(-x));
}
// fp16 hi/lo split store: representation error ~2^-22 relative
__device__ __forceinline__ void split_store(__half* hh, __half* hl,
                                            int idx, float v) {
    __half h = __float2half_rn(v);
    hh[idx] = h;
    hl[idx] = __float2half_rn(v - __half2float(h));
}
__device__ __forceinline__ uint32_t smem_u32(const void* p) {
    uint32_t a;
    asm("{ .reg .u64 t; cvta.to.shared.u64 t, %1; cvt.u32.u64 %0, t; }" : "=r"(a) : "l"(p));
    return a;
}
// mma.sync m16n8k16 fp16 -> fp32
__device__ __forceinline__ void hmma(float* c, const uint32_t* a,
                                     uint32_t b0, uint32_t b1) {
    asm("mma.sync.aligned.m16n8k16.row.col.f32.f16.f16.f32 "
        "{%0,%1,%2,%3}, {%4,%5,%6,%7}, {%8,%9}, {%0,%1,%2,%3};"
        : "+f"(c[0]), "+f"(c[1]), "+f"(c[2]), "+f"(c[3])
        : "r"(a[0]), "r"(a[1]), "r"(a[2]), "r"(a[3]), "r"(b0), "r"(b1));
}
__device__ __forceinline__ void ldsm_x4(uint32_t* a, uint32_t addr) {
    asm volatile("ldmatrix.sync.aligned.m8n8.x4.shared.b16 {%0,%1,%2,%3}, [%4];"
        : "=r"(a[0]), "=r"(a[1]), "=r"(a[2]), "=r"(a[3]) : "r"(addr));
}

// ============================================================
// Dense layer (layers 1 & 2): O = swish(A @ W^T + bias)
// 16 warps x 4 n8-tiles x 2 m16-tiles; 2-term fp16 split
// (Ah*W + Al*W); weight frags via LDG.64, depth-1 prefetch.
// ============================================================
template<int NKIT, int ASTR>
__device__ __forceinline__ void layer_dense(
    const __half* Ah, const __half* Al,
    const uint2* __restrict__ Wp,
    const float* bias,
    __half* Oh, __half* Ol,
    int warp, int lane)
{
    const int t4 = lane & 3;
    const int g = lane >> 2;
    const int nbase = warp * 32;

    float acc[8][4];
#pragma unroll
    for (int i = 0; i < 8; i++)
#pragma unroll
        for (int j = 0; j < 4; j++) acc[i][j] = 0.f;

    const uint32_t aAh = smem_u32(Ah), aAl = smem_u32(Al);
    const int roff0 = (((lane & 15)) * ASTR + ((lane >> 4) * 8)) * 2;
    const int roff1 = (((lane & 15) + 16) * ASTR + ((lane >> 4) * 8)) * 2;

    const uint2* wbase = Wp + ((size_t)(warp * 4) * NKIT) * 32 + lane;

    uint2 bf[4];
#pragma unroll
    for (int nt = 0; nt < 4; nt++)
        bf[nt] = __ldg(wbase + (size_t)nt * NKIT * 32);

#pragma unroll
    for (int kit = 0; kit < NKIT; kit++) {
        const int kb = kit * 32;
        uint32_t ah[2][4], al[2][4];
        ldsm_x4(ah[0], aAh + roff0 + kb);
        ldsm_x4(ah[1], aAh + roff1 + kb);
        ldsm_x4(al[0], aAl + roff0 + kb);
        ldsm_x4(al[1], aAl + roff1 + kb);

        uint2 bn[4];
        if (kit + 1 < NKIT) {
#pragma unroll
            for (int nt = 0; nt < 4; nt++)
                bn[nt] = __ldg(wbase + ((size_t)nt * NKIT + kit + 1) * 32);
        }
        // term 1: Ah * W
#pragma unroll
        for (int nt = 0; nt < 4; nt++)
#pragma unroll
            for (int mt = 0; mt < 2; mt++)
                hmma(acc[nt * 2 + mt], ah[mt], bf[nt].x, bf[nt].y);
        // term 2: Al * W
#pragma unroll
        for (int nt = 0; nt < 4; nt++)
#pragma unroll
            for (int mt = 0; mt < 2; mt++)
                hmma(acc[nt * 2 + mt], al[mt], bf[nt].x, bf[nt].y);

        if (kit + 1 < NKIT) {
#pragma unroll
            for (int nt = 0; nt < 4; nt++) bf[nt] = bn[nt];
        }
    }
    __syncthreads();   // all activation reads done before overwrite
#pragma unroll
    for (int nt = 0; nt < 4; nt++)
#pragma unroll
        for (int mt = 0; mt < 2; mt++) {
            float* c = acc[nt * 2 + mt];
            const int c0 = nbase + nt * 8 + t4 * 2;
            const int r0 = mt * 16 + g;
            const float bv0 = bias[c0], bv1 = bias[c0 + 1];
            split_store(Oh, Ol, r0 * HS + c0,           swishf(c[0] + bv0));
            split_store(Oh, Ol, r0 * HS + c0 + 1,       swishf(c[1] + bv1));
            split_store(Oh, Ol, (r0 + 8) * HS + c0,     swishf(c[2] + bv0));
            split_store(Oh, Ol, (r0 + 8) * HS + c0 + 1, swishf(c[3] + bv1));
        }
}

// ============================================================
// Persistent rollout (TM=32)
// ============================================================
__global__ void __launch_bounds__(NTHREADS) rollout_kernel(
    const float* __restrict__ obs,
    const float* __restrict__ acts,
    const float* __restrict__ b1, const float* __restrict__ b2,
    const float* __restrict__ b3,
    const float* __restrict__ maxlv, const float* __restrict__ minlv,
    const float* __restrict__ noise,
    float* __restrict__ out_obs,
    float* __restrict__ out_rew)
{
    const int tile = blockIdx.x;
    if (tile >= g_ntiles) return;
    const int nrows = g_tileRows[tile];
    const int km    = g_tileK[tile];
    const int start = g_tileStart[tile];

    extern __shared__ char sm[];
    __half* Hh = (__half*)(sm + OFF_HH);
    __half* Hl = (__half*)(sm + OFF_HL);
    __half* Xh = (__half*)(sm + OFF_XH);
    __half* Xl = (__half*)(sm + OFF_XL);
    float* sh_out = (float*)(sm + OFF_OUT);
    float* sb1 = (float*)(sm + OFF_B1);
    float* sb2 = (float*)(sm + OFF_B2);
    float* sb3 = (float*)(sm + OFF_B3);
    __shared__ int rows[TM];

    const int tid  = threadIdx.x;
    const int warp = tid >> 5, lane = tid & 31;
    const int g = lane >> 2, t4 = lane & 3;

    if (tid < TM) rows[tid] = (tid < nrows) ? g_perm[start + tid] : 0;

    for (int i = tid; i < HID; i += NTHREADS) {
        sb1[i] = b1[(size_t)km * HID + i];
        sb2[i] = b2[(size_t)km * HID + i];
    }
    for (int i = tid; i < N3PAD; i += NTHREADS)
        sb3[i] = (i < OUTD) ? b3[(size_t)km * OUTD + i] : 0.f;

    const uint2* Wp1 = g_wp1 + (size_t)km * NT1 * NKIT1 * 32;
    const uint2* Wp2 = g_wp2 + (size_t)km * NT1 * NKIT2 * 32;
    const uint2* Wp3 = g_wp3 + (size_t)km * NT3 * NKIT3 * 32;

    __syncthreads();

    for (int i = tid; i < TM * XS; i += NTHREADS) {
        Xh[i] = __float2half_rn(0.f);
        Xl[i] = __float2half_rn(0.f);
    }
    __syncthreads();
    for (int idx = tid; idx < TM * OBS; idx += NTHREADS) {
        int r = idx >> 6, d = idx & 63;
        float v = (r < nrows) ? obs[(size_t)rows[r] * OBS + d] : 0.f;
        split_store(Xh, Xl, r * XS + d, v);
    }

    for (int t = 0; t < T_STEPS; t++) {
        for (int idx = tid; idx < TM * ACT; idx += NTHREADS) {
            int r = idx >> 4, a = idx & 15;
            float v = (r < nrows) ? acts[((size_t)rows[r] * T_STEPS + t) * ACT + a] : 0.f;
            split_store(Xh, Xl, r * XS + OBS + a, v);
        }
        __syncthreads();

        layer_dense<NKIT1, XS>(Xh, Xl, Wp1, sb1, Hh, Hl, warp, lane);
        __syncthreads();
        layer_dense<NKIT2, HS>(Hh, Hl, Wp2, sb2, Hh, Hl, warp, lane);
        __syncthreads();

        // ===== layer 3: h[32,512] @ W3 -> out[32,129] =====
        {
            float acc[2][2][4];
#pragma unroll
            for (int i = 0; i < 2; i++)
#pragma unroll
                for (int m = 0; m < 2; m++)
#pragma unroll
                    for (int j = 0; j < 4; j++) acc[i][m][j] = 0.f;
            const int ntiles = (warp == 0) ? 2 : 1;
            const int tn[2] = {warp, 16};

            const uint32_t aHh = smem_u32(Hh), aHl = smem_u32(Hl);
            const int roff0 = (((lane & 15)) * HS + ((lane >> 4) * 8)) * 2;
            const int roff1 = (((lane & 15) + 16) * HS + ((lane >> 4) * 8)) * 2;

            const uint2* wq0 = Wp3 + ((size_t)tn[0] * NKIT3) * 32 + lane;
            const uint2* wq1 = Wp3 + ((size_t)tn[1] * NKIT3) * 32 + lane;

            uint2 bf[2];
            bf[0] = __ldg(wq0);
            if (ntiles > 1) bf[1] = __ldg(wq1);

#pragma unroll 4
            for (int kit = 0; kit < NKIT3; kit++) {
                const int kb = kit * 32;
                uint32_t ah[2][4], al[2][4];
                ldsm_x4(ah[0], aHh + roff0 + kb);
                ldsm_x4(ah[1], aHh + roff1 + kb);
                ldsm_x4(al[0], aHl + roff0 + kb);
                ldsm_x4(al[1], aHl + roff1 + kb);

                uint2 bn[2];
                if (kit + 1 < NKIT3) {
                    bn[0] = __ldg(wq0 + (kit + 1) * 32);
                    if (ntiles > 1) bn[1] = __ldg(wq1 + (kit + 1) * 32);
                }
#pragma unroll
                for (int i = 0; i < 2; i++)
                    if (i < ntiles)
#pragma unroll
                        for (int mt = 0; mt < 2; mt++)
                            hmma(acc[i][mt], ah[mt], bf[i].x, bf[i].y);
#pragma unroll
                for (int i = 0; i < 2; i++)
                    if (i < ntiles)
#pragma unroll
                        for (int mt = 0; mt < 2; mt++)
                            hmma(acc[i][mt], al[mt], bf[i].x, bf[i].y);

                if (kit + 1 < NKIT3) { bf[0] = bn[0]; bf[1] = bn[1]; }
            }
            __syncthreads();
            for (int i = 0; i < ntiles; i++) {
                const int c0 = tn[i] * 8 + t4 * 2;
#pragma unroll
                for (int mt = 0; mt < 2; mt++) {
                    float* c = acc[i][mt];
                    const int r0 = mt * 16 + g;
                    if (c0 < OUT_STRIDE) {
                        sh_out[r0 * OUT_STRIDE + c0]       = c[0] + sb3[c0];
                        sh_out[(r0 + 8) * OUT_STRIDE + c0] = c[2] + sb3[c0];
                    }
                    if (c0 + 1 < OUT_STRIDE) {
                        sh_out[r0 * OUT_STRIDE + c0 + 1]       = c[1] + sb3[c0 + 1];
                        sh_out[(r0 + 8) * OUT_STRIDE + c0 + 1] = c[3] + sb3[c0 + 1];
                    }
                }
            }
        }
        __syncthreads();

        // ===== postprocess =====
        const float* nz_t = noise + ((size_t)t * K_ENS + km) * B_TOT * OBS;
        for (int idx = tid; idx < TM * OBS; idx += NTHREADS) {
            int r = idx >> 6, d = idx & 63;
            if (r < nrows) {
                int row = rows[r];
                float mean = sh_out[r * OUT_STRIDE + d];
                float lv   = sh_out[r * OUT_STRIDE + OBS + d];
                float mx = __ldg(maxlv + d), mn = __ldg(minlv + d);
                lv = mx - softplusf(mx - lv);
                lv = mn + softplusf(lv - mn);
                float nz = __ldg(nz_t + (size_t)row * OBS + d);
                float no = fmaf(nz, __expf(0.5f * lv), mean);
                out_obs[((size_t)row * T_STEPS + t) * OBS + d] = no;
                split_store(Xh, Xl, r * XS + d, no);
            }
        }
        if (tid < nrows)
            out_rew[(size_t)rows[tid] * T_STEPS + t] = sh_out[tid * OUT_STRIDE + 128];
        __syncthreads();
    }
}

// ============================================================
// Launch
// ============================================================
extern "C" void kernel_launch(void* const* d_in, const int* in_sizes, int n_in,
                              void* d_out, int out_size) {
    const float* obs   = (const float*)d_in[0];
    const float* acts  = (const float*)d_in[1];
    const float* W1    = (const float*)d_in[2];
    const float* b1    = (const float*)d_in[3];
    const float* W2    = (const float*)d_in[4];
    const float* b2    = (const float*)d_in[5];
    const float* W3    = (const float*)d_in[6];
    const float* b3    = (const float*)d_in[7];
    const float* maxlv = (const float*)d_in[8];
    const float* minlv = (const float*)d_in[9];
    const float* noise = (const float*)d_in[10];
    const int*   assign_raw = (const int*)d_in[11];

    float* out_obs = (float*)d_out;
    float* out_rew = out_obs + (size_t)B_TOT * T_STEPS * OBS;

    uint2 *wp1, *wp2, *wp3;
    cudaGetSymbolAddress((void**)&wp1, g_wp1);
    cudaGetSymbolAddress((void**)&wp2, g_wp2);
    cudaGetSymbolAddress((void**)&wp3, g_wp3);

    cudaFuncSetAttribute(rollout_kernel,
                         cudaFuncAttributeMaxDynamicSharedMemorySize, SMEM_BYTES);

    setup_kernel<<<1, SETUP_THREADS>>>(assign_raw);

    {
        int maxtot = NT1 * NKIT2 * 32;   // 65536 (largest layer)
        pack_all<<<dim3((maxtot + 255) / 256, 3, K_ENS), 256>>>(W1, W2, W3, wp1, wp2, wp3);
    }

    rollout_kernel<<<MAXTILES, NTHREADS, SMEM_BYTES>>>(
        obs, acts, b1, b2, b3, maxlv, minlv, noise, out_obs, out_rew);
}